// round 15
// baseline (speedup 1.0000x reference)
#include <cuda_runtime.h>
#include <cuda_bf16.h>
#include <cstdint>

namespace {

constexpr int VJ = 25, TD = 300, CD = 256, NB = 32;
constexpr int NF   = VJ * TD;     // 7500 flattened (w,t)
constexpr int ASTR = 7504;        // padded agg row stride (16B-aligned rows)
constexpr int BM = 128, BN = 256, BK = 32;
constexpr int NCHUNK = CD / BK;   // 8
constexpr int THREADS = 256;
constexpr int NSTAGE = 3;

// per-stage smem: A fragments (16 KB) | B rows 32 x 260 floats
constexpr int BROW  = 260;                    // floats per B row (256 + 4 pad)
constexpr int OFF_A = 0;
constexpr int OFF_B = 16384;
constexpr int STAGE = OFF_B + BK * BROW * 4;  // 49664
constexpr int SMEM_DYN = NSTAGE * STAGE;      // 148992

// persistent scratch (allocation-free workaround)
__device__ float g_aggt[(size_t)NB * CD * ASTR + 256];  // tf32-rounded agg
__device__ float g_wt[CD * CD];                          // W in fragment order, tf32-rounded

__device__ __forceinline__ uint32_t smem_u32(const void* p) {
    uint32_t a;
    asm("{ .reg .u64 t; cvta.to.shared.u64 t, %1; cvt.u32.u64 %0, t; }" : "=r"(a) : "l"(p));
    return a;
}
__device__ __forceinline__ float tf32r(float v) {
    float r;
    asm("cvt.rna.tf32.f32 %0, %1;" : "=f"(r) : "f"(v));
    return r;
}
__device__ __forceinline__ void cpa16(uint32_t dst, const void* src) {
    asm volatile("cp.async.cg.shared.global [%0], [%1], 16;" :: "r"(dst), "l"(src));
}
__device__ __forceinline__ void lds128(uint32_t* r, uint32_t addr) {
    asm volatile("ld.shared.v4.b32 {%0,%1,%2,%3}, [%4];"
                 : "=r"(r[0]), "=r"(r[1]), "=r"(r[2]), "=r"(r[3]) : "r"(addr));
}
__device__ __forceinline__ uint32_t lds32(uint32_t addr) {
    uint32_t r;
    asm volatile("ld.shared.b32 %0, [%1];" : "=r"(r) : "r"(addr));
    return r;
}
__device__ __forceinline__ void mma_tf32(float* c, const uint32_t* a, uint32_t b0, uint32_t b1) {
    asm volatile(
        "mma.sync.aligned.m16n8k8.row.col.f32.tf32.tf32.f32 "
        "{%0,%1,%2,%3}, {%4,%5,%6,%7}, {%8,%9}, {%0,%1,%2,%3};"
        : "+f"(c[0]), "+f"(c[1]), "+f"(c[2]), "+f"(c[3])
        : "r"(a[0]), "r"(a[1]), "r"(a[2]), "r"(a[3]), "r"(b0), "r"(b1));
}

// ---- fused pre-pass: agg stencil (blocks < 60000) + W fragment repack (blocks >= 60000)
__global__ void prep_all(const float* __restrict__ x, const float* __restrict__ A,
                         const float* __restrict__ W) {
    if (blockIdx.x >= 60000) {
        // W -> tf32-rounded, m16n8k8 A-fragment order.
        // blob index ((rblk*32 + cch)*32 + lane): 4 floats = a0..a3 of tile (rblk*16, cch*8)
        const int i    = (blockIdx.x - 60000) * 256 + threadIdx.x;  // 0..16383
        const int lane = i & 31;
        const int cch  = (i >> 5) & 31;
        const int rblk = i >> 10;
        const int g  = lane >> 2, tg = lane & 3;
        const int R = rblk * 16, C = cch * 8;
        float4 v;
        v.x = tf32r(W[(R + g    ) * CD + C + tg    ]);
        v.y = tf32r(W[(R + g + 8) * CD + C + tg    ]);
        v.z = tf32r(W[(R + g    ) * CD + C + tg + 4]);
        v.w = tf32r(W[(R + g + 8) * CD + C + tg + 4]);
        reinterpret_cast<float4*>(g_wt)[i] = v;
        return;
    }
    // agg = 3-tap stencil over joints, tf32-rounded fp32 (padded rows)
    const int i  = blockIdx.x * 256 + threadIdx.x;  // 15,360,000 float4s exactly
    const int nc = i / 1875;                        // (n,c) row
    const int t4 = (i - nc * 1875) * 4;             // never crosses a w boundary
    const int w  = t4 / TD;
    const float* ps = x + (size_t)nc * NF + t4;
    const float a_s = A[w * VJ + w];
    float4 v = *reinterpret_cast<const float4*>(ps);
    float4 r;
    r.x = a_s * v.x; r.y = a_s * v.y; r.z = a_s * v.z; r.w = a_s * v.w;
    if (w > 0) {
        const float a_p = A[(w - 1) * VJ + w];
        float4 vm = *reinterpret_cast<const float4*>(ps - TD);
        r.x += a_p * vm.x; r.y += a_p * vm.y; r.z += a_p * vm.z; r.w += a_p * vm.w;
    }
    if (w < VJ - 1) {
        const float a_n = A[(w + 1) * VJ + w];
        float4 vp = *reinterpret_cast<const float4*>(ps + TD);
        r.x += a_n * vp.x; r.y += a_n * vp.y; r.z += a_n * vp.z; r.w += a_n * vp.w;
    }
    float4 o = make_float4(tf32r(r.x), tf32r(r.y), tf32r(r.z), tf32r(r.w));
    *reinterpret_cast<float4*>(g_aggt + (size_t)nc * ASTR + t4) = o;
}

// ---- main GEMM: out[n] = W @ agg[n] (+bias), tf32 single-pass, 64x64 warp tiles
__global__ __launch_bounds__(THREADS, 1)
void gemm_kernel(const float* __restrict__ bias, float* __restrict__ out)
{
    extern __shared__ char smem[];
    const uint32_t sb = smem_u32(smem);

    const int tid  = threadIdx.x;
    const int lane = tid & 31;
    const int wid  = tid >> 5;
    const int warp_m = wid & 1;    // 2 warps -> 64 rows each
    const int warp_n = wid >> 1;   // 4 warps -> 64 cols each

    const int nt0 = blockIdx.x * BN;
    const int m   = blockIdx.y;        // M-half
    const int n   = blockIdx.z;        // batch

    float acc[4][8][4];
    #pragma unroll
    for (int a = 0; a < 4; ++a)
        #pragma unroll
        for (int b = 0; b < 8; ++b)
            #pragma unroll
            for (int e = 0; e < 4; ++e) acc[a][b][e] = 0.0f;

    // ---- cp.async producer: A fragment blobs + B rows
    auto load_chunk = [&](int kc, int stg) {
        const uint32_t stb = sb + stg * STAGE;
        // A: 8 rblocks x 4 k8-chunks x 512B = 16 KB (fragment order, verbatim copy)
        #pragma unroll
        for (int q = 0; q < 4; ++q) {
            const int idx = tid + q * 256;            // 0..1023
            const int rl = idx >> 7;                  // 0..7
            const int cl = (idx >> 5) & 3;            // 0..3
            const int l16 = idx & 31;
            const uint32_t dst = stb + OFF_A + (uint32_t)(rl * 2048 + cl * 512 + l16 * 16);
            const size_t so = ((size_t)((8 * m + rl) * 32 + 4 * kc + cl) * 32 + l16) * 4;
            cpa16(dst, g_wt + so);
        }
        // B: 32 k-rows x 64 16B-chunks (rows padded to 260 floats)
        #pragma unroll
        for (int q = 0; q < 8; ++q) {
            const int idx = tid + q * 256;            // 0..2047
            const int k = idx >> 6, cc = idx & 63;
            const uint32_t dst = stb + OFF_B + (uint32_t)(k * (BROW * 4) + cc * 16);
            const size_t so = (size_t)(n * CD + kc * BK + k) * ASTR + nt0 + cc * 4;
            cpa16(dst, g_aggt + so);
        }
        asm volatile("cp.async.commit_group;" ::: "memory");
    };

    load_chunk(0, 0);
    load_chunk(1, 1);

    const int g  = lane >> 2;
    const int tg = lane & 3;
    const uint32_t a_frag_off = OFF_A + (uint32_t)(warp_m * 4 * 2048 + lane * 16);
    // B word address component: (tg + koff)*BROW + n0 + g  (bank = 4tg+g+n0, conflict-free)
    const uint32_t b_off0 = OFF_B + (uint32_t)((tg * BROW + warp_n * 64 + g) * 4);

    for (int kc = 0; kc < NCHUNK; ++kc) {
        // At loop top, chunks kc..kc+1 are in flight -> allow 1 pending group.
        if (kc + 1 < NCHUNK) {
            asm volatile("cp.async.wait_group 1;" ::: "memory");
        } else {
            asm volatile("cp.async.wait_group 0;" ::: "memory");
        }
        // single barrier: all threads finished compute(kc-1), so prefetch into
        // stage (kc+2)%3 (== the stage compute(kc-1) read) is race-free.
        __syncthreads();
        if (kc + 2 < NCHUNK) load_chunk(kc + 2, (kc + 2) % NSTAGE);

        const uint32_t stb = sb + (kc % NSTAGE) * STAGE;
        #pragma unroll
        for (int ks = 0; ks < 4; ++ks) {
            uint32_t a[4][4], b[8][2];
            #pragma unroll
            for (int mt = 0; mt < 4; ++mt)
                lds128(a[mt], stb + a_frag_off + (uint32_t)(mt * 2048 + ks * 512));
            const uint32_t bbase = stb + b_off0 + (uint32_t)(ks * 8 * BROW * 4);
            #pragma unroll
            for (int nt = 0; nt < 8; ++nt) {
                b[nt][0] = lds32(bbase + (uint32_t)(nt * 8 * 4));
                b[nt][1] = lds32(bbase + (uint32_t)((4 * BROW + nt * 8) * 4));
            }
            #pragma unroll
            for (int mt = 0; mt < 4; ++mt)
                #pragma unroll
                for (int nt = 0; nt < 8; ++nt)
                    mma_tf32(acc[mt][nt], a[mt], b[nt][0], b[nt][1]);
        }
    }

    // ---- epilogue: c0=(g,2tg) c1=(g,2tg+1) c2=(g+8,2tg) c3=(g+8,2tg+1)
    #pragma unroll
    for (int mt = 0; mt < 4; ++mt) {
        const int o0 = m * BM + warp_m * 64 + mt * 16 + g;
        const float bv0 = bias[o0];
        const float bv1 = bias[o0 + 8];
        float* row0 = out + ((size_t)n * CD + o0    ) * NF;
        float* row1 = out + ((size_t)n * CD + o0 + 8) * NF;
        #pragma unroll
        for (int nt = 0; nt < 8; ++nt) {
            const int idx = nt0 + warp_n * 64 + nt * 8 + 2 * tg;   // even; NF even
            if (idx < NF) {
                float2 v0 = make_float2(acc[mt][nt][0] + bv0, acc[mt][nt][1] + bv0);
                float2 v1 = make_float2(acc[mt][nt][2] + bv1, acc[mt][nt][3] + bv1);
                *reinterpret_cast<float2*>(row0 + idx) = v0;
                *reinterpret_cast<float2*>(row1 + idx) = v1;
            }
        }
    }
}

} // namespace

extern "C" void kernel_launch(void* const* d_in, const int* in_sizes, int n_in,
                              void* d_out, int out_size) {
    const float* x    = (const float*)d_in[0];
    const float* A    = (const float*)d_in[1];
    const float* W    = (const float*)d_in[2];
    const float* b    = (const float*)d_in[3];
    float*       outp = (float*)d_out;

    prep_all<<<60064, 256>>>(x, A, W);

    cudaFuncSetAttribute(gemm_kernel,
                         cudaFuncAttributeMaxDynamicSharedMemorySize, SMEM_DYN);
    dim3 grid((NF + BN - 1) / BN, 2, NB);   // 30 x 2 x 32 = 1920 CTAs
    gemm_kernel<<<grid, THREADS, SMEM_DYN>>>(b, outp);
}

// round 16
// speedup vs baseline: 1.2096x; 1.2096x over previous
#include <cuda_runtime.h>
#include <cuda_bf16.h>
#include <cstdint>

namespace {

constexpr int VJ = 25, TD = 300, CD = 256, NB = 32;
constexpr int NF   = VJ * TD;     // 7500 flattened (w,t)
constexpr int ASTR = 7504;        // padded agg row stride (16B-aligned rows)
constexpr int BM = 128, BN = 128, BK = 32;
constexpr int NCHUNK = CD / BK;   // 8
constexpr int THREADS = 256;
constexpr int NSTAGE = 3;

// per-stage smem: A fragments (16 KB) | B rows 32 x 132 floats (16896 B)
constexpr int BROW  = 132;                    // floats per B row (128 + 4 pad)
constexpr int OFF_A = 0;
constexpr int OFF_B = 16384;
constexpr int STAGE = OFF_B + BK * BROW * 4;  // 33280
constexpr int OFF_BAR = NSTAGE * STAGE;       // 99840: full[s]@+s*16, empty[s]@+s*16+8
constexpr int SMEM_DYN = OFF_BAR + 64;

// persistent scratch (allocation-free workaround)
__device__ float g_aggt[(size_t)NB * CD * ASTR + 256];  // tf32-rounded agg
__device__ float g_wt[CD * CD];                          // W in fragment order, tf32-rounded

__device__ __forceinline__ uint32_t smem_u32(const void* p) {
    uint32_t a;
    asm("{ .reg .u64 t; cvta.to.shared.u64 t, %1; cvt.u32.u64 %0, t; }" : "=r"(a) : "l"(p));
    return a;
}
__device__ __forceinline__ float tf32r(float v) {
    float r;
    asm("cvt.rna.tf32.f32 %0, %1;" : "=f"(r) : "f"(v));
    return r;
}
__device__ __forceinline__ void cpa16(uint32_t dst, const void* src) {
    asm volatile("cp.async.cg.shared.global [%0], [%1], 16;" :: "r"(dst), "l"(src));
}
__device__ __forceinline__ void lds128(uint32_t* r, uint32_t addr) {
    asm volatile("ld.shared.v4.b32 {%0,%1,%2,%3}, [%4];"
                 : "=r"(r[0]), "=r"(r[1]), "=r"(r[2]), "=r"(r[3]) : "r"(addr));
}
__device__ __forceinline__ uint32_t lds32(uint32_t addr) {
    uint32_t r;
    asm volatile("ld.shared.b32 %0, [%1];" : "=r"(r) : "r"(addr));
    return r;
}
__device__ __forceinline__ void mma_tf32(float* c, const uint32_t* a, uint32_t b0, uint32_t b1) {
    asm volatile(
        "mma.sync.aligned.m16n8k8.row.col.f32.tf32.tf32.f32 "
        "{%0,%1,%2,%3}, {%4,%5,%6,%7}, {%8,%9}, {%0,%1,%2,%3};"
        : "+f"(c[0]), "+f"(c[1]), "+f"(c[2]), "+f"(c[3])
        : "r"(a[0]), "r"(a[1]), "r"(a[2]), "r"(a[3]), "r"(b0), "r"(b1));
}
// ---- mbarrier primitives (sm_80/90 PTX; validated to assemble on compute_103 in R7)
__device__ __forceinline__ void mbar_init(uint32_t a, uint32_t cnt) {
    asm volatile("mbarrier.init.shared.b64 [%0], %1;" :: "r"(a), "r"(cnt) : "memory");
}
__device__ __forceinline__ void mbar_arrive(uint32_t a) {
    asm volatile("mbarrier.arrive.shared.b64 _, [%0];" :: "r"(a) : "memory");
}
__device__ __forceinline__ void cpasync_arrive(uint32_t a) {
    asm volatile("cp.async.mbarrier.arrive.noinc.shared.b64 [%0];" :: "r"(a) : "memory");
}
__device__ __forceinline__ void mbar_wait(uint32_t mbar, uint32_t parity) {
    asm volatile(
        "{\n\t.reg .pred P1;\n\t"
        "WAIT_LOOP_%=:\n\t"
        "mbarrier.try_wait.parity.shared.b64 P1, [%0], %1;\n\t"
        "@P1 bra.uni WAIT_DONE_%=;\n\t"
        "bra.uni WAIT_LOOP_%=;\n\t"
        "WAIT_DONE_%=:\n\t}"
        :: "r"(mbar), "r"(parity) : "memory");
}

// ---- fused pre-pass: agg stencil (blocks < 60000) + W fragment repack (blocks >= 60000)
__global__ void prep_all(const float* __restrict__ x, const float* __restrict__ A,
                         const float* __restrict__ W) {
    if (blockIdx.x >= 60000) {
        // W -> tf32-rounded, m16n8k8 A-fragment order.
        // blob index ((rblk*32 + cch)*32 + lane): 4 floats = a0..a3 of tile (rblk*16, cch*8)
        const int i    = (blockIdx.x - 60000) * 256 + threadIdx.x;  // 0..16383
        const int lane = i & 31;
        const int cch  = (i >> 5) & 31;
        const int rblk = i >> 10;
        const int g  = lane >> 2, tg = lane & 3;
        const int R = rblk * 16, C = cch * 8;
        float4 v;
        v.x = tf32r(W[(R + g    ) * CD + C + tg    ]);
        v.y = tf32r(W[(R + g + 8) * CD + C + tg    ]);
        v.z = tf32r(W[(R + g    ) * CD + C + tg + 4]);
        v.w = tf32r(W[(R + g + 8) * CD + C + tg + 4]);
        reinterpret_cast<float4*>(g_wt)[i] = v;
        return;
    }
    // agg = 3-tap stencil over joints, tf32-rounded fp32 (padded rows)
    const int i  = blockIdx.x * 256 + threadIdx.x;  // 15,360,000 float4s exactly
    const int nc = i / 1875;                        // (n,c) row
    const int t4 = (i - nc * 1875) * 4;             // never crosses a w boundary
    const int w  = t4 / TD;
    const float* ps = x + (size_t)nc * NF + t4;
    const float a_s = A[w * VJ + w];
    float4 v = *reinterpret_cast<const float4*>(ps);
    float4 r;
    r.x = a_s * v.x; r.y = a_s * v.y; r.z = a_s * v.z; r.w = a_s * v.w;
    if (w > 0) {
        const float a_p = A[(w - 1) * VJ + w];
        float4 vm = *reinterpret_cast<const float4*>(ps - TD);
        r.x += a_p * vm.x; r.y += a_p * vm.y; r.z += a_p * vm.z; r.w += a_p * vm.w;
    }
    if (w < VJ - 1) {
        const float a_n = A[(w + 1) * VJ + w];
        float4 vp = *reinterpret_cast<const float4*>(ps + TD);
        r.x += a_n * vp.x; r.y += a_n * vp.y; r.z += a_n * vp.z; r.w += a_n * vp.w;
    }
    float4 o = make_float4(tf32r(r.x), tf32r(r.y), tf32r(r.z), tf32r(r.w));
    *reinterpret_cast<float4*>(g_aggt + (size_t)nc * ASTR + t4) = o;
}

// ---- main GEMM: out[n] = W @ agg[n] (+bias), tf32, mbarrier-ring pipeline
__global__ __launch_bounds__(THREADS, 2)
void gemm_kernel(const float* __restrict__ bias, float* __restrict__ out)
{
    extern __shared__ char smem[];
    const uint32_t sb = smem_u32(smem);

    const int tid  = threadIdx.x;
    const int lane = tid & 31;
    const int wid  = tid >> 5;
    const int warp_m = wid & 1;    // 2 warps -> 64 rows each
    const int warp_n = wid >> 1;   // 4 warps -> 32 cols each

    const int nt0 = blockIdx.x * BN;
    const int m   = blockIdx.y;        // M-half
    const int n   = blockIdx.z;        // batch

    const uint32_t barb = sb + OFF_BAR;
    if (tid == 0) {
        #pragma unroll
        for (int s = 0; s < NSTAGE; ++s) {
            mbar_init(barb + s * 16,     THREADS);   // full[s]: 256 async-arrives
            mbar_init(barb + s * 16 + 8, THREADS);   // empty[s]: 256 consumer arrives
        }
    }
    __syncthreads();

    float acc[4][4][4];
    #pragma unroll
    for (int a = 0; a < 4; ++a)
        #pragma unroll
        for (int b = 0; b < 4; ++b)
            #pragma unroll
            for (int e = 0; e < 4; ++e) acc[a][b][e] = 0.0f;

    // ---- cp.async producer: A fragment blobs + B rows (no commit_group; mbarrier-tracked)
    auto load_chunk = [&](int kc, int stg) {
        const uint32_t stb = sb + stg * STAGE;
        // A: 8 rblocks x 4 k8-chunks x 512B = 16 KB (fragment order, verbatim copy)
        #pragma unroll
        for (int q = 0; q < 4; ++q) {
            const int idx = tid + q * 256;            // 0..1023
            const int rl = idx >> 7;                  // 0..7
            const int cl = (idx >> 5) & 3;            // 0..3
            const int l16 = idx & 31;
            const uint32_t dst = stb + OFF_A + (uint32_t)(rl * 2048 + cl * 512 + l16 * 16);
            const size_t so = ((size_t)((8 * m + rl) * 32 + 4 * kc + cl) * 32 + l16) * 4;
            cpa16(dst, g_wt + so);
        }
        // B: 32 k-rows x 32 16B-chunks (rows padded to 132 floats)
        #pragma unroll
        for (int q = 0; q < 4; ++q) {
            const int idx = tid + q * 256;            // 0..1023
            const int k = idx >> 5, cc = idx & 31;
            const uint32_t dst = stb + OFF_B + (uint32_t)(k * (BROW * 4) + cc * 16);
            const size_t so = (size_t)(n * CD + kc * BK + k) * ASTR + nt0 + cc * 4;
            cpa16(dst, g_aggt + so);
        }
    };

    // produce(kcp): wait stage empty, issue cp.asyncs, schedule async arrive on full
    auto produce = [&](int kcp) {
        const int s = kcp % NSTAGE;
        const int pass = kcp / NSTAGE;
        mbar_wait(barb + s * 16 + 8, (uint32_t)((pass & 1) ^ 1));  // fresh barrier: parity-1 passes
        load_chunk(kcp, s);
        cpasync_arrive(barb + s * 16);
    };

    produce(0);
    produce(1);

    const int g  = lane >> 2;
    const int tg = lane & 3;
    const uint32_t a_frag_off = OFF_A + (uint32_t)(warp_m * 4 * 2048 + lane * 16);
    // B word address component: (tg + koff)*BROW + n0 + g  (bank = 4tg+g+n0, conflict-free)
    const uint32_t b_off0 = OFF_B + (uint32_t)((tg * BROW + warp_n * 32 + g) * 4);

    auto lds_frag = [&](uint32_t stb, int ks, uint32_t a[4][4], uint32_t b[4][2]) {
        #pragma unroll
        for (int mt = 0; mt < 4; ++mt)
            lds128(a[mt], stb + a_frag_off + (uint32_t)(mt * 2048 + ks * 512));
        const uint32_t bbase = stb + b_off0 + (uint32_t)(ks * 8 * BROW * 4);
        #pragma unroll
        for (int nt = 0; nt < 4; ++nt) {
            b[nt][0] = lds32(bbase + (uint32_t)(nt * 8 * 4));
            b[nt][1] = lds32(bbase + (uint32_t)((4 * BROW + nt * 8) * 4));
        }
    };

    for (int kc = 0; kc < NCHUNK; ++kc) {
        // prefetch 2 ahead; its empty-wait blocks only on consumers of kc-1 ARRIVING,
        // not on their full compute of kc — warps desync up to 2 chunks.
        if (kc + 2 < NCHUNK) produce(kc + 2);

        const int s = kc % NSTAGE;
        mbar_wait(barb + s * 16, (uint32_t)((kc / NSTAGE) & 1));   // full[s]

        const uint32_t stb = sb + s * STAGE;
        uint32_t a0[4][4], b0[4][2], a1[4][4], b1[4][2];
        lds_frag(stb, 0, a0, b0);
        #pragma unroll
        for (int ks = 0; ks < 4; ++ks) {
            uint32_t (*ac)[4] = (ks & 1) ? a1 : a0;
            uint32_t (*bc)[2] = (ks & 1) ? b1 : b0;
            if (ks < 3) {                    // prefetch next fragments during MMAs
                uint32_t (*an)[4] = (ks & 1) ? a0 : a1;
                uint32_t (*bn)[2] = (ks & 1) ? b0 : b1;
                lds_frag(stb, ks + 1, an, bn);
            }
            #pragma unroll
            for (int mt = 0; mt < 4; ++mt)
                #pragma unroll
                for (int nt = 0; nt < 4; ++nt)
                    mma_tf32(acc[mt][nt], ac[mt], bc[nt][0], bc[nt][1]);
        }
        mbar_arrive(barb + s * 16 + 8);                            // empty[s]
    }

    // ---- epilogue: c0=(g,2tg) c1=(g,2tg+1) c2=(g+8,2tg) c3=(g+8,2tg+1)
    #pragma unroll
    for (int mt = 0; mt < 4; ++mt) {
        const int o0 = m * BM + warp_m * 64 + mt * 16 + g;
        const float bv0 = bias[o0];
        const float bv1 = bias[o0 + 8];
        float* row0 = out + ((size_t)n * CD + o0    ) * NF;
        float* row1 = out + ((size_t)n * CD + o0 + 8) * NF;
        #pragma unroll
        for (int nt = 0; nt < 4; ++nt) {
            const int idx = nt0 + warp_n * 32 + nt * 8 + 2 * tg;   // even; NF even
            if (idx < NF) {
                float2 v0 = make_float2(acc[mt][nt][0] + bv0, acc[mt][nt][1] + bv0);
                float2 v1 = make_float2(acc[mt][nt][2] + bv1, acc[mt][nt][3] + bv1);
                *reinterpret_cast<float2*>(row0 + idx) = v0;
                *reinterpret_cast<float2*>(row1 + idx) = v1;
            }
        }
    }
}

} // namespace

extern "C" void kernel_launch(void* const* d_in, const int* in_sizes, int n_in,
                              void* d_out, int out_size) {
    const float* x    = (const float*)d_in[0];
    const float* A    = (const float*)d_in[1];
    const float* W    = (const float*)d_in[2];
    const float* b    = (const float*)d_in[3];
    float*       outp = (float*)d_out;

    prep_all<<<60064, 256>>>(x, A, W);

    cudaFuncSetAttribute(gemm_kernel,
                         cudaFuncAttributeMaxDynamicSharedMemorySize, SMEM_DYN);
    dim3 grid((NF + BN - 1) / BN, 2, NB);   // 59 x 2 x 32 = 3776 CTAs
    gemm_kernel<<<grid, THREADS, SMEM_DYN>>>(b, outp);
}